// round 6
// baseline (speedup 1.0000x reference)
#include <cuda_runtime.h>
#include <stdint.h>

// out[b,h,w,:] = graph[b, slic[b,h,w]-1, :]
//   graph: [B=4, S=256, C=128] fp32  -> 128 KiB/batch, L1D-resident (no smem!)
//   slic:  [B=4, 512, 512] int32     -> streamed with evict-first (__ldcs)
//   out:   [B, 512, 512, 128] fp32   -> 512 MiB coalesced STG.128 = roofline
//
// No shared memory: full 2048-thread occupancy; table gathers hit L1D
// (228 KiB carveout, persists across CTAs on the same SM within the launch).

static constexpr int B  = 4;
static constexpr int S  = 256;
static constexpr int C  = 128;
static constexpr int HW = 512 * 512;                  // 262144 (= 2^18)
static constexpr int NPIX = B * HW;                   // 1,048,576

static constexpr int THREADS       = 256;             // 8 warps
static constexpr int PIX_PER_WARP  = 32;
static constexpr int PIX_PER_BLOCK = 8 * PIX_PER_WARP;        // 256
static constexpr int BLOCKS        = NPIX / PIX_PER_BLOCK;    // 4096

__global__ __launch_bounds__(THREADS)
void convert2image_l1_kernel(const float* __restrict__ graph,
                             const int*   __restrict__ slic,
                             float*       __restrict__ out) {
    const int warp = threadIdx.x >> 5;
    const int lane = threadIdx.x & 31;

    // This warp's 32 contiguous pixels (all within one batch: blocks never
    // straddle the 2^18 pixel batch boundary since 256 | 2^18).
    const int pix0 = blockIdx.x * PIX_PER_BLOCK + warp * PIX_PER_WARP;
    const int b    = pix0 >> 18;

    const float4* tab  = reinterpret_cast<const float4*>(graph) + (size_t)b * (S * C / 4); // [S][32]
    const int4*   sid4 = reinterpret_cast<const int4*>(slic) + (pix0 >> 2);                // 8 int4
    float4*       dst  = reinterpret_cast<float4*>(out) + (size_t)pix0 * 32 + lane;

    #pragma unroll 2
    for (int step = 0; step < 8; step++) {            // 4 pixels per step
        // 4 segment ids, warp-uniform broadcast; evict-first so the streaming
        // index read doesn't evict the L1-resident gather table.
        const int4 iv = __ldcs(&sid4[step]);

        // 4 independent L1-hit gathers (512 B each, lanes consecutive 16 B).
        const float4 v0 = __ldg(&tab[(iv.x - 1) * 32 + lane]);
        const float4 v1 = __ldg(&tab[(iv.y - 1) * 32 + lane]);
        const float4 v2 = __ldg(&tab[(iv.z - 1) * 32 + lane]);
        const float4 v3 = __ldg(&tab[(iv.w - 1) * 32 + lane]);

        // 4 coalesced 512 B stores (2 KiB contiguous per warp-step).
        dst[step * 128 +  0] = v0;
        dst[step * 128 + 32] = v1;
        dst[step * 128 + 64] = v2;
        dst[step * 128 + 96] = v3;
    }
}

extern "C" void kernel_launch(void* const* d_in, const int* in_sizes, int n_in,
                              void* d_out, int out_size) {
    const float* graph = (const float*)d_in[0];
    const int*   slic  = (const int*)d_in[1];
    float*       out   = (float*)d_out;

    convert2image_l1_kernel<<<BLOCKS, THREADS>>>(graph, slic, out);
}

// round 7
// speedup vs baseline: 1.1011x; 1.1011x over previous
#include <cuda_runtime.h>
#include <stdint.h>

// out[b,h,w,:] = graph[b, slic[b,h,w]-1, :]
//   graph: [B=4, S=256, C=128] fp32  -> 128 KiB/batch, L1D-resident (no smem)
//   slic:  [B=4, 512, 512] int32     -> streamed (evict-first)
//   out:   [B, 512, 512, 128] fp32   -> 512 MiB stores, written with st.global.cs
//                                       (evict-first: prompt writeback, no L2 churn)

static constexpr int B  = 4;
static constexpr int S  = 256;
static constexpr int C  = 128;
static constexpr int HW = 512 * 512;                  // 2^18
static constexpr int NPIX = B * HW;                   // 1,048,576

static constexpr int THREADS       = 256;             // 8 warps
static constexpr int PIX_PER_WARP  = 32;
static constexpr int PIX_PER_BLOCK = 8 * PIX_PER_WARP;        // 256
static constexpr int BLOCKS        = NPIX / PIX_PER_BLOCK;    // 4096

__global__ __launch_bounds__(THREADS)
void convert2image_cs_kernel(const float* __restrict__ graph,
                             const int*   __restrict__ slic,
                             float*       __restrict__ out) {
    const int warp = threadIdx.x >> 5;
    const int lane = threadIdx.x & 31;

    // This warp's 32 contiguous pixels (blocks never straddle a batch:
    // 256 | 2^18).
    const int pix0 = blockIdx.x * PIX_PER_BLOCK + warp * PIX_PER_WARP;
    const int b    = pix0 >> 18;

    const float4* tab  = reinterpret_cast<const float4*>(graph) + (size_t)b * (S * C / 4); // [S][32]
    const int4*   sid4 = reinterpret_cast<const int4*>(slic) + (pix0 >> 2);                // 8 int4
    float4*       dst  = reinterpret_cast<float4*>(out) + (size_t)pix0 * 32 + lane;

    #pragma unroll
    for (int step = 0; step < 8; step++) {            // 4 pixels per step
        // 4 segment ids, warp-uniform broadcast; evict-first so the index
        // stream never displaces the L1/L2-resident gather table.
        const int4 iv = __ldcs(&sid4[step]);

        // 4 independent gathers, L1-hit (table resident, 228 KiB carveout).
        const float4 v0 = __ldg(&tab[(iv.x - 1) * 32 + lane]);
        const float4 v1 = __ldg(&tab[(iv.y - 1) * 32 + lane]);
        const float4 v2 = __ldg(&tab[(iv.z - 1) * 32 + lane]);
        const float4 v3 = __ldg(&tab[(iv.w - 1) * 32 + lane]);

        // 4 coalesced 512 B streaming stores (evict-first -> prompt, smooth
        // L2->DRAM drain; the output is never re-read).
        __stcs(&dst[step * 128 +  0], v0);
        __stcs(&dst[step * 128 + 32], v1);
        __stcs(&dst[step * 128 + 64], v2);
        __stcs(&dst[step * 128 + 96], v3);
    }
}

extern "C" void kernel_launch(void* const* d_in, const int* in_sizes, int n_in,
                              void* d_out, int out_size) {
    const float* graph = (const float*)d_in[0];
    const int*   slic  = (const int*)d_in[1];
    float*       out   = (float*)d_out;

    convert2image_cs_kernel<<<BLOCKS, THREADS>>>(graph, slic, out);
}